// round 6
// baseline (speedup 1.0000x reference)
#include <cuda_runtime.h>
#include <stdint.h>

// Problem constants (fixed by the reference: NX=41, r_max=6.0, voxel=0.3, K=4, min_sep=3)
#define NXG    41
#define NROWS  (NXG * NXG)       // 1681 rows of 41 voxels
#define GVOX   (NXG * NXG * NXG) // 68921
#define KP     4
#define SEP    3
#define NEGF   (-1.0e9f)
#define VTH    (-1.0e8f)

#define THREADS    384
#define NWARP      12
#define WCH        8                          // rows per warp-chunk
#define WBUF       (WCH * NXG + 4)            // 332 floats (4 slack for align shift)

// Shared-memory layout (bytes)
#define SM_BUF    0                                   // 12 warps * 2 stages * 332 f = 31872
#define SM_ROWMAX (SM_BUF + NWARP * 2 * WBUF * 4)     // 31872
#define SM_ROWK   (SM_ROWMAX + NROWS * 4)             // 38596
#define SM_ROWLO  (SM_ROWK + 1684)                    // 40280
#define SM_XS2    (SM_ROWLO + 1684)                   // 41964
#define SM_YS2    (SM_XS2 + 168)
#define SM_ZZ     (SM_YS2 + 168)
#define SM_ZZS    (SM_ZZ + 168)                       // 21 floats (zz[20+d]), pad 88
#define SM_SWV    (SM_ZZS + 88)
#define SM_SWR    (SM_SWV + 48)
#define SM_PICK   (SM_SWR + 48)
#define SM_PS     (SM_PICK + 4)
#define SM_PG     (SM_PS + 16)
#define SM_PV     (SM_PG + 16)
#define SM_TOTAL  (SM_PV + 16 + 32)                   // ~42.8 KB -> 4 CTAs/SM

#define CP_ASYNC_16(dst, src) \
    asm volatile("cp.async.cg.shared.global [%0], [%1], 16;" :: "r"(dst), "l"(src) : "memory")
#define CP_ASYNC_4(dst, src) \
    asm volatile("cp.async.ca.shared.global [%0], [%1], 4;"  :: "r"(dst), "l"(src) : "memory")
#define CP_COMMIT()  asm volatile("cp.async.commit_group;" ::: "memory")
#define CP_WAIT(n)   asm volatile("cp.async.wait_group %0;" :: "n"(n) : "memory")

static __device__ __forceinline__ uint32_t smem_u32(const void* p) {
    return (uint32_t)__cvta_generic_to_shared(p);
}

// Exact floor(r/41) for 0 <= r < 53773.
static __device__ __forceinline__ int div41(int r) {
    return (int)(((unsigned)r * 51151u) >> 21);
}

// Issue one warp-chunk: h-scalar head to reach 16B global alignment, 16B body,
// scalar tail. dstb = smem byte addr of buffer; sft = float shift matching h.
static __device__ __forceinline__ void issue_wchunk(uint32_t dstb, const float* g0,
                                                    int nelem, int h, int sft, int lane)
{
    if (lane < h) CP_ASYNC_4(dstb + (uint32_t)(sft + lane) * 4u, g0 + lane);
    const int body = nelem - h;
    const int nv = body >> 2;
    for (int vi = lane; vi < nv; vi += 32) {
        const int f = h + 4 * vi;
        CP_ASYNC_16(dstb + (uint32_t)(sft + f) * 4u, g0 + f);
    }
    const int nrem = body & 3;
    if (lane < nrem) {
        const int f = h + 4 * nv + lane;
        CP_ASYNC_4(dstb + (uint32_t)(sft + f) * 4u, g0 + f);
    }
}

// ---------------------------------------------------------------------------
// Fully fused, warp-decoupled double-buffered streaming with per-row valid-k
// intervals. One CTA per (n,c) problem, 384 threads = 12 warps.
__global__ __launch_bounds__(THREADS, 4)
void fused_peaks_kernel(const float* __restrict__ density,
                        const float* __restrict__ grid_xyz,
                        const float* __restrict__ Rmats,
                        const float* __restrict__ tpos,
                        const float* __restrict__ node_mask,
                        float* __restrict__ out,
                        int C)
{
    extern __shared__ char smem[];
    float*   bufs   = (float*)(smem + SM_BUF);
    float*   rowmax = (float*)(smem + SM_ROWMAX);
    uint8_t* rowk   = (uint8_t*)(smem + SM_ROWK);
    uint8_t* rowlo  = (uint8_t*)(smem + SM_ROWLO);
    float*   xs2    = (float*)(smem + SM_XS2);
    float*   ys2    = (float*)(smem + SM_YS2);
    float*   zz     = (float*)(smem + SM_ZZ);
    float*   zzs    = (float*)(smem + SM_ZZS);
    float*   swv    = (float*)(smem + SM_SWV);
    int*     swr    = (int*)(smem + SM_SWR);
    int*     s_pick = (int*)(smem + SM_PICK);
    float*   s_ps   = (float*)(smem + SM_PS);
    int*     s_pg   = (int*)(smem + SM_PG);
    int*     s_pv   = (int*)(smem + SM_PV);

    const int tid  = threadIdx.x;
    const int lane = tid & 31;
    const int w    = tid >> 5;
    const int p    = blockIdx.x;
    const size_t base = (size_t)p * GVOX;   // GVOX % 4 == 1 -> base % 4 == p % 4

    // Warp-private row range and buffers.
    const int rstart = (w * NROWS) / NWARP;
    const int rend   = ((w + 1) * NROWS) / NWARP;
    const int nch    = (rend - rstart + WCH - 1) / WCH;
    float* wb[2] = { bufs + (w * 2 + 0) * WBUF, bufs + (w * 2 + 1) * WBUF };

    // Kick off chunk 0 immediately (overlaps all table building below).
    {
        const int nrows = min(WCH, rend - rstart);
        const long off  = (long)rstart * NXG;
        const int  al   = (int)((base + off) & 3);
        issue_wchunk(smem_u32(wb[0]), density + base + off, nrows * NXG,
                     (4 - al) & 3, al, lane);
        CP_COMMIT();
    }

    // Per-axis squared coords from the ACTUAL grid_xyz input.
    // Sphere test (s<=36.0f) is bit-equivalent to sqrtf(s)<=6.0f under RN.
    if (tid < NXG) {
        float x = grid_xyz[3 * (tid * NXG * NXG) + 0];
        float y = grid_xyz[3 * (tid * NXG) + 1];
        float z = grid_xyz[3 * tid + 2];
        xs2[tid] = __fmul_rn(x, x);
        ys2[tid] = __fmul_rn(y, y);
        zz[tid]  = __fmul_rn(z, z);
    }
    if (tid < 21) {                  // zzs[d] = zz[20+d]; zz is exactly symmetric
        float z = grid_xyz[3 * (tid + 20) + 2];
        zzs[tid] = __fmul_rn(z, z);
    }
    __syncthreads();

    // Per-row valid interval: valid ks = [20-d, 20+d], d = max{d: t2+zzs[d] <= 36}
    // (RN add is monotone, zzs increasing -> predicate monotone -> binary ascent).
    for (int r = tid; r < NROWS; r += THREADS) {
        const int i = div41(r);
        const int j = r - i * NXG;
        const float t2 = __fadd_rn(xs2[i], ys2[j]);
        int d = -1;
        #pragma unroll
        for (int step = 16; step; step >>= 1) {
            int nd = d + step;
            if (nd <= 20 && __fadd_rn(t2, zzs[nd]) <= 36.0f) d = nd;
        }
        rowlo[r] = (uint8_t)(20 - d);      // 21 when row entirely outside sphere
    }
    __syncthreads();

    // ---------------- Phase 1: per-warp double-buffered stream + argmax ------
    for (int c = 0; c < nch; c++) {
        const int next = c + 1;
        if (next < nch) {
            const int row0n  = rstart + next * WCH;
            const int nrowsn = min(WCH, rend - row0n);
            const long offn  = (long)row0n * NXG;
            const int  aln   = (int)((base + offn) & 3);
            issue_wchunk(smem_u32(wb[next & 1]), density + base + offn,
                         nrowsn * NXG, (4 - aln) & 3, aln, lane);
            CP_COMMIT();
            CP_WAIT(1);
        } else {
            CP_WAIT(0);
        }
        __syncwarp();   // cross-lane visibility of chunk c data

        // Quad-per-row: 4 lanes scan fixed k-segments intersected with the
        // valid interval; merge by (value desc, k asc) = global first-index.
        const int row0  = rstart + c * WCH;
        const int nrows = min(WCH, rend - row0);
        const int al    = (int)((base + (long)row0 * NXG) & 3);
        const int lr    = lane >> 2;                 // 0..7
        const int q     = lane & 3;
        const int rr    = min(row0 + lr, NROWS - 1);
        const int klo   = (int)rowlo[rr];
        const int khi   = 40 - klo;
        const int qlo   = 10 * q + (q > 0 ? 1 : 0);  // [0,10][11,20][21,30][31,40]
        const int qhi   = 10 * q + 10;
        const int lo    = max(qlo, klo);
        const int hi    = min(qhi, khi);
        const float* rowp = wb[c & 1] + al + lr * NXG;

        float best = NEGF; int bk = lo;
        for (int k = lo; k <= hi; k++) {
            const float v = rowp[k];
            if (v > best) { best = v; bk = k; }      // strict >: first-k on ties
        }
        #pragma unroll
        for (int off = 1; off <= 2; off <<= 1) {
            const float ov = __shfl_xor_sync(0xffffffffu, best, off);
            const int   ok = __shfl_xor_sync(0xffffffffu, bk, off);
            if (ov > best || (ov == best && ok < bk)) { best = ov; bk = ok; }
        }
        if (q == 0 && lr < nrows) {
            rowmax[row0 + lr] = best;
            rowk[row0 + lr]   = (uint8_t)bk;
        }
        __syncwarp();   // all lanes done with buf[c&1] before it is refilled
    }
    __syncthreads();    // all warps' rowmax/rowk complete

    // ---------------- Phase 2: K iterations of argmax + local NMS ------------
    int pk_i[KP], pk_j[KP], pk_k[KP];
    int npk = 0;   // replicated across threads (derived from shared data)

    for (int it = 0; it < KP; it++) {
        // Block argmax over rowmax[0..1680], first-occurrence tie-break.
        float bv = -__int_as_float(0x7f800000);
        int   br = 0x7fffffff;
        for (int r = tid; r < NROWS; r += THREADS) {
            float v = rowmax[r];
            if (v > bv) { bv = v; br = r; }        // r ascending: ties keep earlier
        }
        #pragma unroll
        for (int off = 16; off; off >>= 1) {
            float ov = __shfl_xor_sync(0xffffffffu, bv, off);
            int   orr = __shfl_xor_sync(0xffffffffu, br, off);
            if (ov > bv || (ov == bv && orr < br)) { bv = ov; br = orr; }
        }
        if (lane == 0) { swv[w] = bv; swr[w] = br; }
        __syncthreads();
        if (w == 0) {
            float v = (lane < NWARP) ? swv[lane] : -__int_as_float(0x7f800000);
            int   r = (lane < NWARP) ? swr[lane] : 0x7fffffff;
            #pragma unroll
            for (int off = 8; off; off >>= 1) {
                float ov = __shfl_xor_sync(0xffffffffu, v, off);
                int   orr = __shfl_xor_sync(0xffffffffu, r, off);
                if (ov > v || (ov == v && orr < r)) { v = ov; r = orr; }
            }
            if (lane == 0) *s_pick = r;
        }
        __syncthreads();

        const int   pr  = *s_pick;
        const float sc  = rowmax[pr];
        const int   pkk = (int)rowk[pr];
        const int   pi  = div41(pr);
        const int   pj  = pr - pi * NXG;
        const bool  valid = sc > VTH;

        if (tid == 0) {
            s_ps[it] = sc;
            s_pg[it] = pr * NXG + pkk;
            s_pv[it] = valid ? 1 : 0;
        }
        if (valid) { pk_i[npk] = pi; pk_j[npk] = pj; pk_k[npk] = pkk; npk++; }
        __syncthreads();   // everyone done reading rowmax before rewrite

        if (it == KP - 1) break;

        // Recompute rows intersecting the new peak's Chebyshev ball, applying
        // suppression from ALL picked-so-far peaks. Thread-per-row, serial scan.
        if (valid) {
            const int i0 = max(pi - SEP, 0), i1 = min(pi + SEP, NXG - 1);
            const int j0 = max(pj - SEP, 0), j1 = min(pj + SEP, NXG - 1);
            const int nj = j1 - j0 + 1;
            const int nr = (i1 - i0 + 1) * nj;
            if (tid < nr) {
                const int i = i0 + tid / nj;
                const int j = j0 + tid % nj;
                const int r = i * NXG + j;
                const float t2 = __fadd_rn(xs2[i], ys2[j]);
                const float* rowg = density + base + (size_t)r * NXG;

                // Which peaks' balls contain this (i,j) column?
                bool in0 = 0 < npk && abs(i - pk_i[0]) <= SEP && abs(j - pk_j[0]) <= SEP;
                bool in1 = 1 < npk && abs(i - pk_i[1]) <= SEP && abs(j - pk_j[1]) <= SEP;
                bool in2 = 2 < npk && abs(i - pk_i[2]) <= SEP && abs(j - pk_j[2]) <= SEP;

                float best = NEGF; int bk = 0;
                #pragma unroll
                for (int k = 0; k < NXG; k++) {
                    const float dv = __ldg(&rowg[k]);   // unconditional: enables MLP
                    const float s  = __fadd_rn(t2, zz[k]);
                    bool sup = (s > 36.0f);
                    if (in0 && abs(k - pk_k[0]) <= SEP) sup = true;
                    if (in1 && abs(k - pk_k[1]) <= SEP) sup = true;
                    if (in2 && abs(k - pk_k[2]) <= SEP) sup = true;
                    const float v = sup ? NEGF : dv;
                    if (v > best) { best = v; bk = k; }
                }
                rowmax[r] = best;
                rowk[r]   = (uint8_t)bk;
            }
        }
        __syncthreads();
    }

    // ---------------- Epilogue: transform + write outputs --------------------
    // Output layout: coords_local [NC,K,3] | coords_global [NC,K,3] |
    //                scores [NC,K] | mask [NC,K]  (all float32)
    if (tid < KP) {
        const int kk = tid;
        const int n  = p / C;
        const int NC = gridDim.x;

        const float sc    = s_ps[kk];
        const bool  valid = (s_pv[kk] != 0);
        const int   g     = s_pg[kk];

        float x = 0.f, y = 0.f, z = 0.f;
        if (valid) {
            x = grid_xyz[3 * g + 0];
            y = grid_xyz[3 * g + 1];
            z = grid_xyz[3 * g + 2];
        }
        const float nm = node_mask[n];
        const float* R = Rmats + (size_t)n * 9;
        const float* t = tpos  + (size_t)n * 3;
        const float gx = R[0] * x + R[1] * y + R[2] * z + t[0];
        const float gy = R[3] * x + R[4] * y + R[5] * z + t[1];
        const float gz = R[6] * x + R[7] * y + R[8] * z + t[2];

        float* CL = out;
        float* CG = out + (size_t)NC * KP * 3;
        float* SC = out + (size_t)NC * KP * 6;
        float* MS = SC  + (size_t)NC * KP;

        const size_t o3 = ((size_t)p * KP + kk) * 3;
        CL[o3 + 0] = x * nm;  CL[o3 + 1] = y * nm;  CL[o3 + 2] = z * nm;
        CG[o3 + 0] = gx * nm; CG[o3 + 1] = gy * nm; CG[o3 + 2] = gz * nm;
        SC[(size_t)p * KP + kk] = (valid ? sc : NEGF) * nm;
        MS[(size_t)p * KP + kk] = (valid && nm != 0.0f) ? 1.0f : 0.0f;
    }
}

extern "C" void kernel_launch(void* const* d_in, const int* in_sizes, int n_in,
                              void* d_out, int out_size)
{
    // Input order per reference setup_inputs():
    // 0: density [B,N,C,G] f32   1: grid_xyz [G,3] f32   2: sphere_mask (unused)
    // 3: coords_int (unused)     4: Rmats [B,N,3,3] f32  5: tpos [B,N,3] f32
    // 6: node_mask [B,N] f32
    const float* density   = (const float*)d_in[0];
    const float* grid_xyz  = (const float*)d_in[1];
    const float* Rmats     = (const float*)d_in[4];
    const float* tposp     = (const float*)d_in[5];
    const float* node_mask = (const float*)d_in[6];
    float* out = (float*)d_out;

    const int NC = in_sizes[0] / GVOX;      // B*N*C = 512
    const int N  = in_sizes[4] / 9;         // B*N   = 128
    const int C  = NC / N;                  // 4
    (void)n_in; (void)out_size;

    static int smem_set = 0;
    if (!smem_set) {
        cudaFuncSetAttribute(fused_peaks_kernel,
                             cudaFuncAttributeMaxDynamicSharedMemorySize, SM_TOTAL);
        smem_set = 1;
    }
    fused_peaks_kernel<<<NC, THREADS, SM_TOTAL>>>(density, grid_xyz, Rmats, tposp,
                                                  node_mask, out, C);
}

// round 7
// speedup vs baseline: 1.3120x; 1.3120x over previous
#include <cuda_runtime.h>
#include <stdint.h>

// Problem constants (fixed by the reference: NX=41, r_max=6.0, voxel=0.3, K=4, min_sep=3)
#define NXG    41
#define NROWS  (NXG * NXG)       // 1681 rows of 41 voxels
#define GVOX   (NXG * NXG * NXG) // 68921
#define KP     4
#define SEP    3
#define NEGF   (-1.0e9f)
#define VTH    (-1.0e8f)

#define THREADS 256
#define NWARP   8
#define WCH     16                            // rows per warp-chunk
#define WBUF    (WCH * NXG + 8)               // 664 floats: <=3 head shift + <=3 round-up
                                              // 664*4 = 2656 B, multiple of 16

// Shared-memory layout (bytes); buffer base 16B-aligned, WBUF*4 mult of 16.
#define SM_BUF    0                                   // 8*2*664*4 = 42496
#define SM_MBAR   (SM_BUF + NWARP * 2 * WBUF * 4)     // 8 warps * 2 * 8B = 128
#define SM_ROWMAX (SM_MBAR + 128)                     // 6724
#define SM_ROWK   (SM_ROWMAX + NROWS * 4)             // 1684
#define SM_XS2    (SM_ROWK + 1684)                    // 168
#define SM_YS2    (SM_XS2 + 168)
#define SM_ZZ     (SM_YS2 + 168)
#define SM_SWV    (SM_ZZ + 168)
#define SM_SWR    (SM_SWV + 32)
#define SM_PICK   (SM_SWR + 32)
#define SM_PS     (SM_PICK + 4)
#define SM_PG     (SM_PS + 16)
#define SM_PV     (SM_PG + 16)
#define SM_TOTAL  (SM_PV + 16 + 32)                   // ~50.6 KB -> 4 CTAs/SM

#define CP_ASYNC_4(dst, src) \
    asm volatile("cp.async.ca.shared.global [%0], [%1], 4;"  :: "r"(dst), "l"(src) : "memory")
#define CP_COMMIT()  asm volatile("cp.async.commit_group;" ::: "memory")
#define CP_WAIT0()   asm volatile("cp.async.wait_group 0;" ::: "memory")

#define MBAR_INIT(mbar, cnt) \
    asm volatile("mbarrier.init.shared.b64 [%0], %1;" :: "r"(mbar), "r"(cnt) : "memory")
#define MBAR_EXPECT_TX(mbar, bytes) \
    asm volatile("mbarrier.arrive.expect_tx.shared.b64 _, [%0], %1;" :: "r"(mbar), "r"(bytes) : "memory")
#define FENCE_PROXY_ASYNC() asm volatile("fence.proxy.async.shared::cta;" ::: "memory")

#define MBAR_WAIT(mbar, par) do {                                              \
    uint32_t _m = (mbar); uint32_t _p = (par); uint32_t _d;                    \
    asm volatile("{\n\t.reg .pred p;\n\t"                                      \
        "mbarrier.try_wait.parity.acquire.cta.shared::cta.b64 p, [%1], %2;\n\t"\
        "selp.b32 %0, 1, 0, p;\n\t}"                                           \
        : "=r"(_d) : "r"(_m), "r"(_p) : "memory");                             \
    if (!_d) {                                                                 \
        asm volatile("{\n\t.reg .pred P1;\n\t"                                 \
            "WL_%=:\n\t"                                                       \
            "mbarrier.try_wait.parity.acquire.cta.shared::cta.b64 P1, [%0], %1, 0x989680;\n\t" \
            "@P1 bra.uni WD_%=;\n\t"                                           \
            "bra.uni WL_%=;\n\t"                                               \
            "WD_%=:\n\t}"                                                      \
            :: "r"(_m), "r"(_p) : "memory");                                   \
    }                                                                          \
} while (0)

#define BULK_LD(dst, src, bytes, mbar) \
    asm volatile("cp.async.bulk.shared::cluster.global.mbarrier::complete_tx::bytes " \
                 "[%0], [%1], %2, [%3];" \
                 :: "r"(dst), "l"(src), "r"(bytes), "r"(mbar) : "memory")

static __device__ __forceinline__ uint32_t smem_u32(const void* p) {
    return (uint32_t)__cvta_generic_to_shared(p);
}

// Exact floor(r/41) for 0 <= r < 53773.
static __device__ __forceinline__ int div41(int r) {
    return (int)(((unsigned)r * 51151u) >> 21);
}

// ---------------------------------------------------------------------------
// Fully fused, warp-decoupled double-buffered streaming via cp.async.bulk
// (TMA): one instruction per 2.6KB chunk instead of per-16B LDGSTS (rt=8cyc),
// which was the measured bottleneck. One CTA per (n,c) problem.
__global__ __launch_bounds__(THREADS, 4)
void fused_peaks_kernel(const float* __restrict__ density,
                        const float* __restrict__ grid_xyz,
                        const float* __restrict__ Rmats,
                        const float* __restrict__ tpos,
                        const float* __restrict__ node_mask,
                        float* __restrict__ out,
                        int C)
{
    extern __shared__ char smem[];
    float*   bufs   = (float*)(smem + SM_BUF);
    float*   rowmax = (float*)(smem + SM_ROWMAX);
    uint8_t* rowk   = (uint8_t*)(smem + SM_ROWK);
    float*   xs2    = (float*)(smem + SM_XS2);
    float*   ys2    = (float*)(smem + SM_YS2);
    float*   zz     = (float*)(smem + SM_ZZ);
    float*   swv    = (float*)(smem + SM_SWV);
    int*     swr    = (int*)(smem + SM_SWR);
    int*     s_pick = (int*)(smem + SM_PICK);
    float*   s_ps   = (float*)(smem + SM_PS);
    int*     s_pg   = (int*)(smem + SM_PG);
    int*     s_pv   = (int*)(smem + SM_PV);

    const int tid  = threadIdx.x;
    const int lane = tid & 31;
    const int w    = tid >> 5;
    const int p    = blockIdx.x;
    const size_t base    = (size_t)p * GVOX;        // base % 4 == p % 4
    const size_t total_f = (size_t)gridDim.x * GVOX;

    // Warp-private row range, buffers, mbarriers (one per stage).
    const int rstart = (w * NROWS) >> 3;
    const int rend   = ((w + 1) * NROWS) >> 3;
    const int nch    = (rend - rstart + WCH - 1) / WCH;
    float* wb[2] = { bufs + (w * 2 + 0) * WBUF, bufs + (w * 2 + 1) * WBUF };
    const uint32_t mb0 = smem_u32(smem + SM_MBAR) + (uint32_t)w * 16u;

    if (lane == 0) { MBAR_INIT(mb0, 1); MBAR_INIT(mb0 + 8, 1); }
    __syncwarp();
    FENCE_PROXY_ASYNC();

    int tailflag = 0;   // set iff a rare cp.async tail was used (uniform per warp)

    // Issue one chunk's bulk copy (lane 0). Returns tail count handled via cp.async.
    auto issue_chunk = [&](int c) {
        const int row0  = rstart + c * WCH;
        const int nrows = min(WCH, rend - row0);
        const size_t need_start = base + (size_t)row0 * NXG;
        const size_t srcA = need_start & ~(size_t)3;          // 16B-aligned float idx
        size_t endA = (need_start + (size_t)nrows * NXG + 3) & ~(size_t)3;
        int tail = 0;
        if (endA > total_f) { endA -= 4; tail = 1; }          // never for NC%4==0
        const uint32_t bytes = (uint32_t)(endA - srcA) * 4u;
        const uint32_t dstb  = smem_u32(wb[c & 1]);
        const uint32_t mbar  = mb0 + (uint32_t)(c & 1) * 8u;
        if (lane == 0) {
            MBAR_EXPECT_TX(mbar, bytes);
            BULK_LD(dstb, density + srcA, bytes, mbar);
        }
        if (tail) {
            const size_t need_end = need_start + (size_t)nrows * NXG;
            const int nrem = (int)(need_end - endA);          // 1..4
            if (lane < nrem)
                CP_ASYNC_4(dstb + (uint32_t)(endA - srcA + lane) * 4u,
                           density + endA + lane);
            CP_COMMIT();
            tailflag = 1;
        }
    };

    issue_chunk(0);    // overlaps table building below

    // Per-axis squared coords from the ACTUAL grid_xyz input.
    // Sphere test (s<=36.0f) is bit-equivalent to sqrtf(s)<=6.0f under RN.
    if (tid < NXG) {
        float x = grid_xyz[3 * (tid * NXG * NXG) + 0];
        float y = grid_xyz[3 * (tid * NXG) + 1];
        float z = grid_xyz[3 * tid + 2];
        xs2[tid] = __fmul_rn(x, x);
        ys2[tid] = __fmul_rn(y, y);
        zz[tid]  = __fmul_rn(z, z);
    }
    __syncthreads();   // tables visible to all warps

    // ---------------- Phase 1: per-warp double-buffered stream + argmax ------
    for (int c = 0; c < nch; c++) {
        if (c + 1 < nch) issue_chunk(c + 1);

        // Wait chunk c: stage (c&1), parity = (c>>1)&1 (each stage reused ~7x).
        MBAR_WAIT(mb0 + (uint32_t)(c & 1) * 8u, (uint32_t)((c >> 1) & 1));
        if (tailflag) { CP_WAIT0(); tailflag = 0; }
        __syncwarp();

        // Thread-pair per row: even lane scans k in [0,21), odd k in [21,41).
        const int row0  = rstart + c * WCH;
        const int nrows = min(WCH, rend - row0);
        const int sft   = (int)((base + (size_t)row0 * NXG) & 3);
        const int lr    = lane >> 1;                 // 0..15
        const int half  = lane & 1;
        const int r     = min(row0 + lr, NROWS - 1);
        const int i     = div41(r);
        const int j     = r - i * NXG;
        const float t2  = __fadd_rn(xs2[i], ys2[j]);
        const float* rowp = wb[c & 1] + sft + lr * NXG + half * 21;
        const int kb    = half * 21;
        const int cnt   = half ? 20 : 21;

        float best = NEGF; int bk = kb;
        #pragma unroll
        for (int kk = 0; kk < 21; kk++) {
            if (kk < cnt) {
                const int k = kb + kk;
                const float sv = __fadd_rn(t2, zz[k]);
                const float v  = (sv <= 36.0f) ? rowp[kk] : NEGF;
                if (v > best) { best = v; bk = k; }   // strict >: first-k on ties
            }
        }
        // Merge halves (odd ks all > even ks, so strict > keeps lower k on ties)
        const float vo = __shfl_down_sync(0xffffffffu, best, 1);
        const int   ko = __shfl_down_sync(0xffffffffu, bk, 1);
        if (half == 0 && lr < nrows) {
            if (vo > best) { best = vo; bk = ko; }
            rowmax[row0 + lr] = best;
            rowk[row0 + lr]   = (uint8_t)bk;
        }
        __syncwarp();   // all lanes done with buf[c&1] before it is refilled
    }
    __syncthreads();    // all warps' rowmax/rowk complete

    // ---------------- Phase 2: K iterations of argmax + local NMS ------------
    int pk_i[KP], pk_j[KP], pk_k[KP];
    int npk = 0;   // replicated across threads (derived from shared data)

    for (int it = 0; it < KP; it++) {
        // Block argmax over rowmax[0..1680], first-occurrence tie-break.
        float bv = -__int_as_float(0x7f800000);
        int   br = 0x7fffffff;
        for (int r = tid; r < NROWS; r += THREADS) {
            float v = rowmax[r];
            if (v > bv) { bv = v; br = r; }        // r ascending: ties keep earlier
        }
        #pragma unroll
        for (int off = 16; off; off >>= 1) {
            float ov = __shfl_xor_sync(0xffffffffu, bv, off);
            int   orr = __shfl_xor_sync(0xffffffffu, br, off);
            if (ov > bv || (ov == bv && orr < br)) { bv = ov; br = orr; }
        }
        if (lane == 0) { swv[w] = bv; swr[w] = br; }
        __syncthreads();
        if (w == 0) {
            float v = (lane < NWARP) ? swv[lane] : -__int_as_float(0x7f800000);
            int   r = (lane < NWARP) ? swr[lane] : 0x7fffffff;
            #pragma unroll
            for (int off = 4; off; off >>= 1) {
                float ov = __shfl_xor_sync(0xffffffffu, v, off);
                int   orr = __shfl_xor_sync(0xffffffffu, r, off);
                if (ov > v || (ov == v && orr < r)) { v = ov; r = orr; }
            }
            if (lane == 0) *s_pick = r;
        }
        __syncthreads();

        const int   pr  = *s_pick;
        const float sc  = rowmax[pr];
        const int   pkk = (int)rowk[pr];
        const int   pi  = div41(pr);
        const int   pj  = pr - pi * NXG;
        const bool  valid = sc > VTH;

        if (tid == 0) {
            s_ps[it] = sc;
            s_pg[it] = pr * NXG + pkk;
            s_pv[it] = valid ? 1 : 0;
        }
        if (valid) { pk_i[npk] = pi; pk_j[npk] = pj; pk_k[npk] = pkk; npk++; }
        __syncthreads();   // everyone done reading rowmax before rewrite

        if (it == KP - 1) break;

        // Recompute rows intersecting the new peak's Chebyshev ball, applying
        // suppression from ALL picked-so-far peaks. Thread-per-row, serial scan.
        if (valid) {
            const int i0 = max(pi - SEP, 0), i1 = min(pi + SEP, NXG - 1);
            const int j0 = max(pj - SEP, 0), j1 = min(pj + SEP, NXG - 1);
            const int nj = j1 - j0 + 1;
            const int nr = (i1 - i0 + 1) * nj;
            if (tid < nr) {
                const int i = i0 + tid / nj;
                const int j = j0 + tid % nj;
                const int r = i * NXG + j;
                const float t2 = __fadd_rn(xs2[i], ys2[j]);
                const float* rowg = density + base + (size_t)r * NXG;

                // Which peaks' balls contain this (i,j) column?
                bool in0 = 0 < npk && abs(i - pk_i[0]) <= SEP && abs(j - pk_j[0]) <= SEP;
                bool in1 = 1 < npk && abs(i - pk_i[1]) <= SEP && abs(j - pk_j[1]) <= SEP;
                bool in2 = 2 < npk && abs(i - pk_i[2]) <= SEP && abs(j - pk_j[2]) <= SEP;

                float best = NEGF; int bk = 0;
                #pragma unroll
                for (int k = 0; k < NXG; k++) {
                    const float dv = __ldg(&rowg[k]);   // unconditional: enables MLP
                    const float s  = __fadd_rn(t2, zz[k]);
                    bool sup = (s > 36.0f);
                    if (in0 && abs(k - pk_k[0]) <= SEP) sup = true;
                    if (in1 && abs(k - pk_k[1]) <= SEP) sup = true;
                    if (in2 && abs(k - pk_k[2]) <= SEP) sup = true;
                    const float v = sup ? NEGF : dv;
                    if (v > best) { best = v; bk = k; }
                }
                rowmax[r] = best;
                rowk[r]   = (uint8_t)bk;
            }
        }
        __syncthreads();
    }

    // ---------------- Epilogue: transform + write outputs --------------------
    // Output layout: coords_local [NC,K,3] | coords_global [NC,K,3] |
    //                scores [NC,K] | mask [NC,K]  (all float32)
    if (tid < KP) {
        const int kk = tid;
        const int n  = p / C;
        const int NC = gridDim.x;

        const float sc    = s_ps[kk];
        const bool  valid = (s_pv[kk] != 0);
        const int   g     = s_pg[kk];

        float x = 0.f, y = 0.f, z = 0.f;
        if (valid) {
            x = grid_xyz[3 * g + 0];
            y = grid_xyz[3 * g + 1];
            z = grid_xyz[3 * g + 2];
        }
        const float nm = node_mask[n];
        const float* R = Rmats + (size_t)n * 9;
        const float* t = tpos  + (size_t)n * 3;
        const float gx = R[0] * x + R[1] * y + R[2] * z + t[0];
        const float gy = R[3] * x + R[4] * y + R[5] * z + t[1];
        const float gz = R[6] * x + R[7] * y + R[8] * z + t[2];

        float* CL = out;
        float* CG = out + (size_t)NC * KP * 3;
        float* SC = out + (size_t)NC * KP * 6;
        float* MS = SC  + (size_t)NC * KP;

        const size_t o3 = ((size_t)p * KP + kk) * 3;
        CL[o3 + 0] = x * nm;  CL[o3 + 1] = y * nm;  CL[o3 + 2] = z * nm;
        CG[o3 + 0] = gx * nm; CG[o3 + 1] = gy * nm; CG[o3 + 2] = gz * nm;
        SC[(size_t)p * KP + kk] = (valid ? sc : NEGF) * nm;
        MS[(size_t)p * KP + kk] = (valid && nm != 0.0f) ? 1.0f : 0.0f;
    }
}

extern "C" void kernel_launch(void* const* d_in, const int* in_sizes, int n_in,
                              void* d_out, int out_size)
{
    // Input order per reference setup_inputs():
    // 0: density [B,N,C,G] f32   1: grid_xyz [G,3] f32   2: sphere_mask (unused)
    // 3: coords_int (unused)     4: Rmats [B,N,3,3] f32  5: tpos [B,N,3] f32
    // 6: node_mask [B,N] f32
    const float* density   = (const float*)d_in[0];
    const float* grid_xyz  = (const float*)d_in[1];
    const float* Rmats     = (const float*)d_in[4];
    const float* tposp     = (const float*)d_in[5];
    const float* node_mask = (const float*)d_in[6];
    float* out = (float*)d_out;

    const int NC = in_sizes[0] / GVOX;      // B*N*C = 512
    const int N  = in_sizes[4] / 9;         // B*N   = 128
    const int C  = NC / N;                  // 4
    (void)n_in; (void)out_size;

    static int smem_set = 0;
    if (!smem_set) {
        cudaFuncSetAttribute(fused_peaks_kernel,
                             cudaFuncAttributeMaxDynamicSharedMemorySize, SM_TOTAL);
        smem_set = 1;
    }
    fused_peaks_kernel<<<NC, THREADS, SM_TOTAL>>>(density, grid_xyz, Rmats, tposp,
                                                  node_mask, out, C);
}